// round 1
// baseline (speedup 1.0000x reference)
#include <cuda_runtime.h>
#include <cuda_bf16.h>
#include <math.h>

// Problem constants
#define DIM       2048
#define HEADS     32
#define DIM_HEAD  64
#define BATCH     2
#define SEQ       2048
#define ROWS      (BATCH * SEQ)          // 4096
#define DIM_INNER (HEADS * DIM_HEAD)     // 2048

// ---------------------------------------------------------------------------
// Scratch (device globals — no allocation allowed)
// ---------------------------------------------------------------------------
__device__ float g_xn[ROWS * DIM];          // 32 MB  rmsnorm output
__device__ float g_q [ROWS * DIM_INNER];    // 32 MB  q projection (then roped)
__device__ float g_kv[ROWS * 2 * DIM_INNER];// 64 MB  k|v projection (k roped)
__device__ float g_o [ROWS * DIM_INNER];    // 32 MB  attention output

// ---------------------------------------------------------------------------
// 1) RMSNorm: xn = x / max(||x||,1e-12) * sqrt(DIM) * gamma   (row-wise)
// ---------------------------------------------------------------------------
__global__ __launch_bounds__(256) void rmsnorm_kernel(
    const float* __restrict__ x, const float* __restrict__ gamma,
    float* __restrict__ xn)
{
    const int row = blockIdx.x;
    const float* xr = x + (size_t)row * DIM;
    float v[8];
    float ss = 0.f;
#pragma unroll
    for (int i = 0; i < 8; i++) {
        v[i] = xr[threadIdx.x + 256 * i];
        ss += v[i] * v[i];
    }
    __shared__ float red[8];
#pragma unroll
    for (int o = 16; o; o >>= 1) ss += __shfl_xor_sync(0xffffffffu, ss, o);
    if ((threadIdx.x & 31) == 0) red[threadIdx.x >> 5] = ss;
    __syncthreads();
    if (threadIdx.x < 32) {
        float s2 = (threadIdx.x < 8) ? red[threadIdx.x] : 0.f;
#pragma unroll
        for (int o = 4; o; o >>= 1) s2 += __shfl_xor_sync(0xffffffffu, s2, o);
        if (threadIdx.x == 0) red[0] = s2;
    }
    __syncthreads();
    const float norm  = sqrtf(red[0]);
    const float scale = 45.25483399593904f / fmaxf(norm, 1e-12f);  // sqrt(2048)
    float* xo = xn + (size_t)row * DIM;
#pragma unroll
    for (int i = 0; i < 8; i++) {
        const int c = threadIdx.x + 256 * i;
        xo[c] = v[i] * scale * gamma[c];
    }
}

// ---------------------------------------------------------------------------
// 2) SGEMM: C[M,N] = A[M,K] @ B[K,N], all row-major, M%128==N%128==K%8==0
//    128x128 block tile, 8x8 per thread, 256 threads
// ---------------------------------------------------------------------------
__global__ __launch_bounds__(256) void sgemm128(
    const float* __restrict__ A, const float* __restrict__ B,
    float* __restrict__ C, int M, int N, int K)
{
    __shared__ float As[8][128];
    __shared__ float Bs[8][128];

    const int brow = blockIdx.y * 128;
    const int bcol = blockIdx.x * 128;
    const int t = threadIdx.x;

    const int arow = t >> 1;            // 0..127
    const int acol = (t & 1) << 2;      // 0 or 4
    const int brw  = t >> 5;            // 0..7
    const int bcl  = (t & 31) << 2;     // 0..124

    const int tr = (t >> 4) << 3;       // thread row base (0..120)
    const int tc = (t & 15) << 3;       // thread col base (0..120)

    float acc[8][8];
#pragma unroll
    for (int i = 0; i < 8; i++)
#pragma unroll
        for (int j = 0; j < 8; j++) acc[i][j] = 0.f;

    const float* Ap = A + (size_t)(brow + arow) * K + acol;
    const float* Bp = B + (size_t)brw * N + bcol + bcl;

    for (int k0 = 0; k0 < K; k0 += 8) {
        float4 av = *(const float4*)(Ap + k0);
        As[acol + 0][arow] = av.x;
        As[acol + 1][arow] = av.y;
        As[acol + 2][arow] = av.z;
        As[acol + 3][arow] = av.w;
        *(float4*)(&Bs[brw][bcl]) = *(const float4*)(Bp + (size_t)k0 * N);
        __syncthreads();
#pragma unroll
        for (int kk = 0; kk < 8; kk++) {
            float4 ra0 = *(const float4*)(&As[kk][tr]);
            float4 ra1 = *(const float4*)(&As[kk][tr + 4]);
            float4 rb0 = *(const float4*)(&Bs[kk][tc]);
            float4 rb1 = *(const float4*)(&Bs[kk][tc + 4]);
            float ra[8] = {ra0.x, ra0.y, ra0.z, ra0.w, ra1.x, ra1.y, ra1.z, ra1.w};
            float rb[8] = {rb0.x, rb0.y, rb0.z, rb0.w, rb1.x, rb1.y, rb1.z, rb1.w};
#pragma unroll
            for (int i = 0; i < 8; i++)
#pragma unroll
                for (int j = 0; j < 8; j++) acc[i][j] += ra[i] * rb[j];
        }
        __syncthreads();
    }

#pragma unroll
    for (int i = 0; i < 8; i++) {
        float* Cp = C + (size_t)(brow + tr + i) * N + bcol + tc;
        float4 v0 = {acc[i][0], acc[i][1], acc[i][2], acc[i][3]};
        float4 v1 = {acc[i][4], acc[i][5], acc[i][6], acc[i][7]};
        *(float4*)(Cp)     = v0;
        *(float4*)(Cp + 4) = v1;
    }
}

// ---------------------------------------------------------------------------
// 3) RoPE (in-place). t rows are [ROWS], head layout h*64+d within rowstride.
//    out[d]    = t[d]*cos(p[d])    - t[d+32]*sin(p[d])
//    out[d+32] = t[d+32]*cos(p[d+32]) + t[d]*sin(p[d+32])
// ---------------------------------------------------------------------------
__global__ __launch_bounds__(256) void rope_kernel(
    float* __restrict__ t, const float* __restrict__ rot, int rowstride)
{
    const int idx = blockIdx.x * 256 + threadIdx.x;  // ROWS*32*32 total
    const int d   = idx & 31;
    const int h   = (idx >> 5) & 31;
    const int row = idx >> 10;
    const int n   = row & (SEQ - 1);
    const float p1 = rot[n * 64 + d];
    const float p2 = rot[n * 64 + d + 32];
    float* base = t + (size_t)row * rowstride + h * 64;
    const float a  = base[d];
    const float bv = base[d + 32];
    base[d]      = a  * __cosf(p1) - bv * __sinf(p1);
    base[d + 32] = bv * __cosf(p2) + a  * __sinf(p2);
}

// ---------------------------------------------------------------------------
// 4) Causal flash attention, fp32. One CTA = (64-query tile, head, batch).
//    smem (dynamic, 69632 B): Qt[d][r], Kt[d][c], Vs[c][d], Ps[r][c], stride 68
// ---------------------------------------------------------------------------
#define SROW 68
__global__ __launch_bounds__(256) void attn_kernel(
    const float* __restrict__ q, const float* __restrict__ kv,
    float* __restrict__ o)
{
    extern __shared__ float sm[];
    float* Qt = sm;                 // [64][SROW]  d-major
    float* Kt = Qt + 64 * SROW;     // [64][SROW]  d-major
    float* Vs = Kt + 64 * SROW;     // [64][SROW]  c-major
    float* Ps = Vs + 64 * SROW;     // [64][SROW]  r-major

    const int t  = threadIdx.x;
    const int tx = t & 15;          // col group  (keys / dims)
    const int ty = t >> 4;          // row group  (queries)
    const int qt = blockIdx.x;      // 0..31
    const int h  = blockIdx.y;
    const int b  = blockIdx.z;

    const size_t qbase  = (size_t)b * SEQ * DIM_INNER + (size_t)h * 64;       // stride 2048
    const size_t kvbase = (size_t)b * SEQ * (2 * DIM_INNER) + (size_t)h * 64; // stride 4096
    const int i0 = qt * 64;
    const float scale = 0.125f;     // 1/sqrt(64)

    // Load Q tile (pre-scaled), transposed to d-major
    for (int e = t; e < 4096; e += 256) {
        const int r = e >> 6, d = e & 63;
        Qt[d * SROW + r] = q[qbase + (size_t)(i0 + r) * DIM_INNER + d] * scale;
    }

    float m[4], l[4], acc[4][4];
#pragma unroll
    for (int i = 0; i < 4; i++) {
        m[i] = -INFINITY; l[i] = 0.f;
#pragma unroll
        for (int j = 0; j < 4; j++) acc[i][j] = 0.f;
    }
    __syncthreads();

    for (int jt = 0; jt <= qt; jt++) {
        const int j0 = jt * 64;
        // Load K (d-major) and V (c-major)
        for (int e = t; e < 4096; e += 256) {
            const int n = e >> 6, d = e & 63;
            const size_t g = kvbase + (size_t)(j0 + n) * (2 * DIM_INNER);
            Kt[d * SROW + n] = kv[g + d];
            Vs[n * SROW + d] = kv[g + DIM_INNER + d];
        }
        __syncthreads();

        // S = Q @ K^T  (each thread: rows ty*4.., cols tx*4..)
        float s[4][4];
#pragma unroll
        for (int i = 0; i < 4; i++)
#pragma unroll
            for (int j = 0; j < 4; j++) s[i][j] = 0.f;
#pragma unroll 4
        for (int d = 0; d < 64; d++) {
            float4 qv = *(const float4*)(Qt + d * SROW + ty * 4);
            float4 kx = *(const float4*)(Kt + d * SROW + tx * 4);
            const float qa[4] = {qv.x, qv.y, qv.z, qv.w};
            const float ka[4] = {kx.x, kx.y, kx.z, kx.w};
#pragma unroll
            for (int i = 0; i < 4; i++)
#pragma unroll
                for (int j = 0; j < 4; j++) s[i][j] += qa[i] * ka[j];
        }
        if (jt == qt) {  // causal mask on the diagonal tile (c > r)
#pragma unroll
            for (int i = 0; i < 4; i++)
#pragma unroll
                for (int j = 0; j < 4; j++)
                    if (tx * 4 + j > ty * 4 + i) s[i][j] = -INFINITY;
        }

        // Row max over the 16 tx-lanes (half-warp shuffles)
        float tm[4];
#pragma unroll
        for (int i = 0; i < 4; i++) {
            float v = fmaxf(fmaxf(s[i][0], s[i][1]), fmaxf(s[i][2], s[i][3]));
#pragma unroll
            for (int o = 8; o; o >>= 1) v = fmaxf(v, __shfl_xor_sync(0xffffffffu, v, o));
            tm[i] = v;
        }
        float alpha[4], ts[4];
#pragma unroll
        for (int i = 0; i < 4; i++) {
            const float mn = fmaxf(m[i], tm[i]);
            alpha[i] = __expf(m[i] - mn);
            m[i] = mn;
            ts[i] = 0.f;
        }
        // P = exp(S - m), store row-major, accumulate row sums
#pragma unroll
        for (int i = 0; i < 4; i++) {
            float p0 = __expf(s[i][0] - m[i]);
            float p1 = __expf(s[i][1] - m[i]);
            float p2 = __expf(s[i][2] - m[i]);
            float p3 = __expf(s[i][3] - m[i]);
            ts[i] = p0 + p1 + p2 + p3;
            float4 pv = {p0, p1, p2, p3};
            *(float4*)(Ps + (ty * 4 + i) * SROW + tx * 4) = pv;
        }
#pragma unroll
        for (int i = 0; i < 4; i++) {
            float v = ts[i];
#pragma unroll
            for (int o = 8; o; o >>= 1) v += __shfl_xor_sync(0xffffffffu, v, o);
            l[i] = l[i] * alpha[i] + v;
#pragma unroll
            for (int j = 0; j < 4; j++) acc[i][j] *= alpha[i];
        }
        __syncthreads();

        // O += P @ V  (thread: rows ty*4.., dims tx*4..)
#pragma unroll 4
        for (int c = 0; c < 64; c++) {
            float4 vv = *(const float4*)(Vs + c * SROW + tx * 4);
#pragma unroll
            for (int i = 0; i < 4; i++) {
                const float p = Ps[(ty * 4 + i) * SROW + c];
                acc[i][0] += p * vv.x;
                acc[i][1] += p * vv.y;
                acc[i][2] += p * vv.z;
                acc[i][3] += p * vv.w;
            }
        }
        __syncthreads();
    }

    // Normalize and write out (same layout as q)
#pragma unroll
    for (int i = 0; i < 4; i++) {
        const float inv = 1.0f / l[i];
        const int r = i0 + ty * 4 + i;
        float4 ov = {acc[i][0] * inv, acc[i][1] * inv, acc[i][2] * inv, acc[i][3] * inv};
        *(float4*)(o + qbase + (size_t)r * DIM_INNER + tx * 4) = ov;
    }
}

// ---------------------------------------------------------------------------
// Host launcher
// ---------------------------------------------------------------------------
extern "C" void kernel_launch(void* const* d_in, const int* in_sizes, int n_in,
                              void* d_out, int out_size)
{
    const float* x     = (const float*)d_in[0];
    const float* rot   = (const float*)d_in[1];
    const float* gamma = (const float*)d_in[2];
    const float* Wq    = (const float*)d_in[3];
    const float* Wkv   = (const float*)d_in[4];
    const float* Wout  = (const float*)d_in[5];
    float* out = (float*)d_out;

    float *xn, *qb, *kvb, *ob;
    cudaGetSymbolAddress((void**)&xn,  g_xn);
    cudaGetSymbolAddress((void**)&qb,  g_q);
    cudaGetSymbolAddress((void**)&kvb, g_kv);
    cudaGetSymbolAddress((void**)&ob,  g_o);

    static bool attr_set = false;
    if (!attr_set) {
        cudaFuncSetAttribute(attn_kernel,
                             cudaFuncAttributeMaxDynamicSharedMemorySize,
                             4 * 64 * SROW * (int)sizeof(float));
        attr_set = true;
    }

    // 1) RMSNorm
    rmsnorm_kernel<<<ROWS, 256>>>(x, gamma, xn);
    // 2) Projections
    sgemm128<<<dim3(DIM_INNER / 128, ROWS / 128), 256>>>(xn, Wq,  qb,  ROWS, DIM_INNER,     DIM);
    sgemm128<<<dim3(2 * DIM_INNER / 128, ROWS / 128), 256>>>(xn, Wkv, kvb, ROWS, 2 * DIM_INNER, DIM);
    // 3) RoPE on q and on k half of kv
    rope_kernel<<<(ROWS * 32 * 32) / 256, 256>>>(qb,  rot, DIM_INNER);
    rope_kernel<<<(ROWS * 32 * 32) / 256, 256>>>(kvb, rot, 2 * DIM_INNER);
    // 4) Causal attention
    attn_kernel<<<dim3(SEQ / 64, HEADS, BATCH), 256,
                  4 * 64 * SROW * (int)sizeof(float)>>>(qb, kvb, ob);
    // 5) Output projection
    sgemm128<<<dim3(DIM / 128, ROWS / 128), 256>>>(ob, Wout, out, ROWS, DIM, DIM);
}

// round 2
// speedup vs baseline: 2.1093x; 2.1093x over previous
#include <cuda_runtime.h>
#include <cuda_bf16.h>
#include <math.h>
#include <stdint.h>

// Problem constants
#define DIM       2048
#define HEADS     32
#define DIM_HEAD  64
#define BATCH     2
#define SEQ       2048
#define ROWS      (BATCH * SEQ)          // 4096
#define DIM_INNER (HEADS * DIM_HEAD)     // 2048

// ---------------------------------------------------------------------------
// Scratch (device globals — no allocation allowed)
// ---------------------------------------------------------------------------
__device__ float g_xn[ROWS * DIM];            // 32 MB  rmsnorm output (tf32-rounded)
__device__ float g_q [ROWS * DIM_INNER];      // 32 MB  q projection (then roped)
__device__ float g_kv[ROWS * 2 * DIM_INNER];  // 64 MB  k|v projection (k roped)
__device__ float g_o [ROWS * DIM_INNER];      // 32 MB  attention output (tf32-rounded)
__device__ float g_wq  [DIM * DIM_INNER];     // 16 MB  tf32-rounded weights
__device__ float g_wkv [DIM * 2 * DIM_INNER]; // 32 MB
__device__ float g_wout[DIM_INNER * DIM];     // 16 MB

__device__ __forceinline__ float to_tf32(float x) {
    uint32_t u;
    asm("cvt.rna.tf32.f32 %0, %1;" : "=r"(u) : "f"(x));
    return __uint_as_float(u);
}

// ---------------------------------------------------------------------------
// 0) Weight rounding to tf32 (once per call; ~negligible)
// ---------------------------------------------------------------------------
__global__ __launch_bounds__(256) void wcvt_kernel(
    const float* __restrict__ in, float* __restrict__ out)
{
    const int i = (blockIdx.x * 256 + threadIdx.x) * 4;
    float4 v = *(const float4*)(in + i);
    v.x = to_tf32(v.x); v.y = to_tf32(v.y);
    v.z = to_tf32(v.z); v.w = to_tf32(v.w);
    *(float4*)(out + i) = v;
}

// ---------------------------------------------------------------------------
// 1) RMSNorm (output rounded to tf32 — it is only consumed by tf32 GEMMs)
// ---------------------------------------------------------------------------
__global__ __launch_bounds__(256) void rmsnorm_kernel(
    const float* __restrict__ x, const float* __restrict__ gamma,
    float* __restrict__ xn)
{
    const int row = blockIdx.x;
    const float* xr = x + (size_t)row * DIM;
    float v[8];
    float ss = 0.f;
#pragma unroll
    for (int i = 0; i < 8; i++) {
        v[i] = xr[threadIdx.x + 256 * i];
        ss += v[i] * v[i];
    }
    __shared__ float red[8];
#pragma unroll
    for (int o = 16; o; o >>= 1) ss += __shfl_xor_sync(0xffffffffu, ss, o);
    if ((threadIdx.x & 31) == 0) red[threadIdx.x >> 5] = ss;
    __syncthreads();
    if (threadIdx.x < 32) {
        float s2 = (threadIdx.x < 8) ? red[threadIdx.x] : 0.f;
#pragma unroll
        for (int o = 4; o; o >>= 1) s2 += __shfl_xor_sync(0xffffffffu, s2, o);
        if (threadIdx.x == 0) red[0] = s2;
    }
    __syncthreads();
    const float norm  = sqrtf(red[0]);
    const float scale = 45.25483399593904f / fmaxf(norm, 1e-12f);  // sqrt(2048)
    float* xo = xn + (size_t)row * DIM;
#pragma unroll
    for (int i = 0; i < 8; i++) {
        const int c = threadIdx.x + 256 * i;
        xo[c] = to_tf32(v[i] * scale * gamma[c]);
    }
}

// ---------------------------------------------------------------------------
// 2) TF32 tensor-core GEMM: C[M,N] = A[M,K] @ B[K,N], row-major.
//    CTA tile 128x128, BK=16, 256 threads = 8 warps (2 m x 4 n),
//    warp tile 64x32 via mma.sync.m16n8k8 (4 m-tiles x 4 n-tiles).
//    cp.async double-buffered smem; inputs pre-rounded to tf32.
// ---------------------------------------------------------------------------
#define CP_ASYNC16(dst, src) \
    asm volatile("cp.async.cg.shared.global [%0], [%1], 16;\n" :: "r"(dst), "l"(src))

__global__ __launch_bounds__(256) void gemm_tf32(
    const float* __restrict__ A, const float* __restrict__ B,
    float* __restrict__ C, int M, int N, int K)
{
    __shared__ float As[2][128][20];   // [buf][m][k]  (16 -> 20 pad: conflict-free frags)
    __shared__ float Bs[2][16][136];   // [buf][k][n]  (128 -> 136 pad)

    const int t    = threadIdx.x;
    const int lane = t & 31;
    const int warp = t >> 5;
    const int wm   = (warp >> 2) * 64;   // warp m offset (0,64)
    const int wn   = (warp & 3) * 32;    // warp n offset (0..96)
    const int grp  = lane >> 2;          // 0..7
    const int qd   = lane & 3;           // 0..3

    const int brow = blockIdx.y * 128;
    const int bcol = blockIdx.x * 128;

    const uint32_t As_b = (uint32_t)__cvta_generic_to_shared(&As[0][0][0]);
    const uint32_t Bs_b = (uint32_t)__cvta_generic_to_shared(&Bs[0][0][0]);

    float acc[4][4][4];
#pragma unroll
    for (int i = 0; i < 4; i++)
#pragma unroll
        for (int j = 0; j < 4; j++)
#pragma unroll
            for (int r = 0; r < 4; r++) acc[i][j][r] = 0.f;

    // ---- async copy of one k-stage ----
    auto copy_stage = [&](int k0, int buf) {
#pragma unroll
        for (int i = 0; i < 2; i++) {                 // A: 128x16 floats
            const int c  = t + 256 * i;
            const int r  = c >> 2;
            const int ko = (c & 3) << 2;
            const float* src = A + (size_t)(brow + r) * K + k0 + ko;
            CP_ASYNC16(As_b + (((buf << 7) + r) * 20 + ko) * 4, src);
        }
#pragma unroll
        for (int i = 0; i < 2; i++) {                 // B: 16x128 floats
            const int c  = t + 256 * i;
            const int r  = c >> 5;
            const int no = (c & 31) << 2;
            const float* src = B + (size_t)(k0 + r) * N + bcol + no;
            CP_ASYNC16(Bs_b + (((buf << 4) + r) * 136 + no) * 4, src);
        }
    };

    const int nIter = K >> 4;       // K/16
    copy_stage(0, 0);
    asm volatile("cp.async.commit_group;\n");

    for (int it = 0; it < nIter; it++) {
        if (it + 1 < nIter) copy_stage((it + 1) << 4, (it + 1) & 1);
        asm volatile("cp.async.commit_group;\n");
        asm volatile("cp.async.wait_group %0;\n" :: "n"(1));
        __syncthreads();

        const int buf = it & 1;
#pragma unroll
        for (int k8 = 0; k8 < 16; k8 += 8) {
            uint32_t af[4][4], bf[4][2];
#pragma unroll
            for (int mt = 0; mt < 4; mt++) {
                const int rA = wm + mt * 16 + grp;
                af[mt][0] = __float_as_uint(As[buf][rA    ][k8 + qd    ]);
                af[mt][1] = __float_as_uint(As[buf][rA + 8][k8 + qd    ]);
                af[mt][2] = __float_as_uint(As[buf][rA    ][k8 + qd + 4]);
                af[mt][3] = __float_as_uint(As[buf][rA + 8][k8 + qd + 4]);
            }
#pragma unroll
            for (int nt = 0; nt < 4; nt++) {
                const int cB = wn + nt * 8 + grp;
                bf[nt][0] = __float_as_uint(Bs[buf][k8 + qd    ][cB]);
                bf[nt][1] = __float_as_uint(Bs[buf][k8 + qd + 4][cB]);
            }
#pragma unroll
            for (int mt = 0; mt < 4; mt++)
#pragma unroll
                for (int nt = 0; nt < 4; nt++) {
                    asm volatile(
                        "mma.sync.aligned.m16n8k8.row.col.f32.tf32.tf32.f32 "
                        "{%0,%1,%2,%3}, {%4,%5,%6,%7}, {%8,%9}, {%0,%1,%2,%3};\n"
                        : "+f"(acc[mt][nt][0]), "+f"(acc[mt][nt][1]),
                          "+f"(acc[mt][nt][2]), "+f"(acc[mt][nt][3])
                        : "r"(af[mt][0]), "r"(af[mt][1]),
                          "r"(af[mt][2]), "r"(af[mt][3]),
                          "r"(bf[nt][0]), "r"(bf[nt][1]));
                }
        }
        __syncthreads();
    }

    // Epilogue
#pragma unroll
    for (int mt = 0; mt < 4; mt++) {
        const int row0 = brow + wm + mt * 16 + grp;
#pragma unroll
        for (int nt = 0; nt < 4; nt++) {
            const int col0 = bcol + wn + nt * 8 + qd * 2;
            float2 v0 = {acc[mt][nt][0], acc[mt][nt][1]};
            float2 v1 = {acc[mt][nt][2], acc[mt][nt][3]};
            *(float2*)(C + (size_t)row0 * N + col0)       = v0;
            *(float2*)(C + (size_t)(row0 + 8) * N + col0) = v1;
        }
    }
}

// ---------------------------------------------------------------------------
// 3) RoPE (in-place), fp32
// ---------------------------------------------------------------------------
__global__ __launch_bounds__(256) void rope_kernel(
    float* __restrict__ t, const float* __restrict__ rot, int rowstride)
{
    const int idx = blockIdx.x * 256 + threadIdx.x;  // ROWS*32*32 total
    const int d   = idx & 31;
    const int h   = (idx >> 5) & 31;
    const int row = idx >> 10;
    const int n   = row & (SEQ - 1);
    const float p1 = rot[n * 64 + d];
    const float p2 = rot[n * 64 + d + 32];
    float* base = t + (size_t)row * rowstride + h * 64;
    const float a  = base[d];
    const float bv = base[d + 32];
    base[d]      = a  * __cosf(p1) - bv * __sinf(p1);
    base[d + 32] = bv * __cosf(p2) + a  * __sinf(p2);
}

// ---------------------------------------------------------------------------
// 4) Causal flash attention, fp32 (output rounded to tf32 for the out-proj)
// ---------------------------------------------------------------------------
#define SROW 68
__global__ __launch_bounds__(256) void attn_kernel(
    const float* __restrict__ q, const float* __restrict__ kv,
    float* __restrict__ o)
{
    extern __shared__ float sm[];
    float* Qt = sm;                 // [64][SROW]  d-major
    float* Kt = Qt + 64 * SROW;     // [64][SROW]  d-major
    float* Vs = Kt + 64 * SROW;     // [64][SROW]  c-major
    float* Ps = Vs + 64 * SROW;     // [64][SROW]  r-major

    const int t  = threadIdx.x;
    const int tx = t & 15;
    const int ty = t >> 4;
    const int qt = blockIdx.x;
    const int h  = blockIdx.y;
    const int b  = blockIdx.z;

    const size_t qbase  = (size_t)b * SEQ * DIM_INNER + (size_t)h * 64;
    const size_t kvbase = (size_t)b * SEQ * (2 * DIM_INNER) + (size_t)h * 64;
    const int i0 = qt * 64;
    const float scale = 0.125f;

    for (int e = t; e < 4096; e += 256) {
        const int r = e >> 6, d = e & 63;
        Qt[d * SROW + r] = q[qbase + (size_t)(i0 + r) * DIM_INNER + d] * scale;
    }

    float m[4], l[4], acc[4][4];
#pragma unroll
    for (int i = 0; i < 4; i++) {
        m[i] = -INFINITY; l[i] = 0.f;
#pragma unroll
        for (int j = 0; j < 4; j++) acc[i][j] = 0.f;
    }
    __syncthreads();

    for (int jt = 0; jt <= qt; jt++) {
        const int j0 = jt * 64;
        for (int e = t; e < 4096; e += 256) {
            const int n = e >> 6, d = e & 63;
            const size_t g = kvbase + (size_t)(j0 + n) * (2 * DIM_INNER);
            Kt[d * SROW + n] = kv[g + d];
            Vs[n * SROW + d] = kv[g + DIM_INNER + d];
        }
        __syncthreads();

        float s[4][4];
#pragma unroll
        for (int i = 0; i < 4; i++)
#pragma unroll
            for (int j = 0; j < 4; j++) s[i][j] = 0.f;
#pragma unroll 4
        for (int d = 0; d < 64; d++) {
            float4 qv = *(const float4*)(Qt + d * SROW + ty * 4);
            float4 kx = *(const float4*)(Kt + d * SROW + tx * 4);
            const float qa[4] = {qv.x, qv.y, qv.z, qv.w};
            const float ka[4] = {kx.x, kx.y, kx.z, kx.w};
#pragma unroll
            for (int i = 0; i < 4; i++)
#pragma unroll
                for (int j = 0; j < 4; j++) s[i][j] += qa[i] * ka[j];
        }
        if (jt == qt) {
#pragma unroll
            for (int i = 0; i < 4; i++)
#pragma unroll
                for (int j = 0; j < 4; j++)
                    if (tx * 4 + j > ty * 4 + i) s[i][j] = -INFINITY;
        }

        float tm[4];
#pragma unroll
        for (int i = 0; i < 4; i++) {
            float v = fmaxf(fmaxf(s[i][0], s[i][1]), fmaxf(s[i][2], s[i][3]));
#pragma unroll
            for (int o = 8; o; o >>= 1) v = fmaxf(v, __shfl_xor_sync(0xffffffffu, v, o));
            tm[i] = v;
        }
        float alpha[4], ts[4];
#pragma unroll
        for (int i = 0; i < 4; i++) {
            const float mn = fmaxf(m[i], tm[i]);
            alpha[i] = __expf(m[i] - mn);
            m[i] = mn;
            ts[i] = 0.f;
        }
#pragma unroll
        for (int i = 0; i < 4; i++) {
            float p0 = __expf(s[i][0] - m[i]);
            float p1 = __expf(s[i][1] - m[i]);
            float p2 = __expf(s[i][2] - m[i]);
            float p3 = __expf(s[i][3] - m[i]);
            ts[i] = p0 + p1 + p2 + p3;
            float4 pv = {p0, p1, p2, p3};
            *(float4*)(Ps + (ty * 4 + i) * SROW + tx * 4) = pv;
        }
#pragma unroll
        for (int i = 0; i < 4; i++) {
            float v = ts[i];
#pragma unroll
            for (int o = 8; o; o >>= 1) v += __shfl_xor_sync(0xffffffffu, v, o);
            l[i] = l[i] * alpha[i] + v;
#pragma unroll
            for (int j = 0; j < 4; j++) acc[i][j] *= alpha[i];
        }
        __syncthreads();

#pragma unroll 4
        for (int c = 0; c < 64; c++) {
            float4 vv = *(const float4*)(Vs + c * SROW + tx * 4);
#pragma unroll
            for (int i = 0; i < 4; i++) {
                const float p = Ps[(ty * 4 + i) * SROW + c];
                acc[i][0] += p * vv.x;
                acc[i][1] += p * vv.y;
                acc[i][2] += p * vv.z;
                acc[i][3] += p * vv.w;
            }
        }
        __syncthreads();
    }

#pragma unroll
    for (int i = 0; i < 4; i++) {
        const float inv = 1.0f / l[i];
        const int r = i0 + ty * 4 + i;
        float4 ov = {to_tf32(acc[i][0] * inv), to_tf32(acc[i][1] * inv),
                     to_tf32(acc[i][2] * inv), to_tf32(acc[i][3] * inv)};
        *(float4*)(o + qbase + (size_t)r * DIM_INNER + tx * 4) = ov;
    }
}

// ---------------------------------------------------------------------------
// Host launcher
// ---------------------------------------------------------------------------
extern "C" void kernel_launch(void* const* d_in, const int* in_sizes, int n_in,
                              void* d_out, int out_size)
{
    const float* x     = (const float*)d_in[0];
    const float* rot   = (const float*)d_in[1];
    const float* gamma = (const float*)d_in[2];
    const float* Wq    = (const float*)d_in[3];
    const float* Wkv   = (const float*)d_in[4];
    const float* Wout  = (const float*)d_in[5];
    float* out = (float*)d_out;

    float *xn, *qb, *kvb, *ob, *wq, *wkv, *wout;
    cudaGetSymbolAddress((void**)&xn,   g_xn);
    cudaGetSymbolAddress((void**)&qb,   g_q);
    cudaGetSymbolAddress((void**)&kvb,  g_kv);
    cudaGetSymbolAddress((void**)&ob,   g_o);
    cudaGetSymbolAddress((void**)&wq,   g_wq);
    cudaGetSymbolAddress((void**)&wkv,  g_wkv);
    cudaGetSymbolAddress((void**)&wout, g_wout);

    static bool attr_set = false;
    if (!attr_set) {
        cudaFuncSetAttribute(attn_kernel,
                             cudaFuncAttributeMaxDynamicSharedMemorySize,
                             4 * 64 * SROW * (int)sizeof(float));
        attr_set = true;
    }

    // 0) tf32-round the weights into scratch
    wcvt_kernel<<<(DIM * DIM_INNER) / 1024, 256>>>(Wq, wq);
    wcvt_kernel<<<(DIM * 2 * DIM_INNER) / 1024, 256>>>(Wkv, wkv);
    wcvt_kernel<<<(DIM_INNER * DIM) / 1024, 256>>>(Wout, wout);
    // 1) RMSNorm (tf32-rounded output)
    rmsnorm_kernel<<<ROWS, 256>>>(x, gamma, xn);
    // 2) Projections on tensor cores
    gemm_tf32<<<dim3(DIM_INNER / 128, ROWS / 128), 256>>>(xn, wq,  qb,  ROWS, DIM_INNER,     DIM);
    gemm_tf32<<<dim3(2 * DIM_INNER / 128, ROWS / 128), 256>>>(xn, wkv, kvb, ROWS, 2 * DIM_INNER, DIM);
    // 3) RoPE
    rope_kernel<<<(ROWS * 32 * 32) / 256, 256>>>(qb,  rot, DIM_INNER);
    rope_kernel<<<(ROWS * 32 * 32) / 256, 256>>>(kvb, rot, 2 * DIM_INNER);
    // 4) Causal attention (fp32)
    attn_kernel<<<dim3(SEQ / 64, HEADS, BATCH), 256,
                  4 * 64 * SROW * (int)sizeof(float)>>>(qb, kvb, ob);
    // 5) Output projection on tensor cores
    gemm_tf32<<<dim3(DIM / 128, ROWS / 128), 256>>>(ob, wout, out, ROWS, DIM, DIM);
}

// round 3
// speedup vs baseline: 3.0289x; 1.4360x over previous
#include <cuda_runtime.h>
#include <cuda_bf16.h>
#include <math.h>
#include <stdint.h>

// Problem constants
#define DIM       2048
#define HEADS     32
#define DIM_HEAD  64
#define BATCH     2
#define SEQ       2048
#define ROWS      (BATCH * SEQ)          // 4096
#define DIM_INNER (HEADS * DIM_HEAD)     // 2048

// ---------------------------------------------------------------------------
// Scratch (device globals — no allocation allowed)
// ---------------------------------------------------------------------------
__device__ float g_xn[ROWS * DIM];
__device__ float g_q [ROWS * DIM_INNER];
__device__ float g_kv[ROWS * 2 * DIM_INNER];
__device__ float g_o [ROWS * DIM_INNER];
__device__ float g_wq  [DIM * DIM_INNER];
__device__ float g_wkv [DIM * 2 * DIM_INNER];
__device__ float g_wout[DIM_INNER * DIM];

__device__ __forceinline__ float to_tf32(float x) {
    uint32_t u;
    asm("cvt.rna.tf32.f32 %0, %1;" : "=r"(u) : "f"(x));
    return __uint_as_float(u);
}
__device__ __forceinline__ uint32_t tf32u(float x) {
    uint32_t u;
    asm("cvt.rna.tf32.f32 %0, %1;" : "=r"(u) : "f"(x));
    return u;
}

// ---------------------------------------------------------------------------
// 0) Weight rounding to tf32
// ---------------------------------------------------------------------------
__global__ __launch_bounds__(256) void wcvt_kernel(
    const float* __restrict__ in, float* __restrict__ out)
{
    const int i = (blockIdx.x * 256 + threadIdx.x) * 4;
    float4 v = *(const float4*)(in + i);
    v.x = to_tf32(v.x); v.y = to_tf32(v.y);
    v.z = to_tf32(v.z); v.w = to_tf32(v.w);
    *(float4*)(out + i) = v;
}

// ---------------------------------------------------------------------------
// 1) RMSNorm (tf32-rounded output)
// ---------------------------------------------------------------------------
__global__ __launch_bounds__(256) void rmsnorm_kernel(
    const float* __restrict__ x, const float* __restrict__ gamma,
    float* __restrict__ xn)
{
    const int row = blockIdx.x;
    const float* xr = x + (size_t)row * DIM;
    float v[8];
    float ss = 0.f;
#pragma unroll
    for (int i = 0; i < 8; i++) {
        v[i] = xr[threadIdx.x + 256 * i];
        ss += v[i] * v[i];
    }
    __shared__ float red[8];
#pragma unroll
    for (int o = 16; o; o >>= 1) ss += __shfl_xor_sync(0xffffffffu, ss, o);
    if ((threadIdx.x & 31) == 0) red[threadIdx.x >> 5] = ss;
    __syncthreads();
    if (threadIdx.x < 32) {
        float s2 = (threadIdx.x < 8) ? red[threadIdx.x] : 0.f;
#pragma unroll
        for (int o = 4; o; o >>= 1) s2 += __shfl_xor_sync(0xffffffffu, s2, o);
        if (threadIdx.x == 0) red[0] = s2;
    }
    __syncthreads();
    const float norm  = sqrtf(red[0]);
    const float scale = 45.25483399593904f / fmaxf(norm, 1e-12f);
    float* xo = xn + (size_t)row * DIM;
#pragma unroll
    for (int i = 0; i < 8; i++) {
        const int c = threadIdx.x + 256 * i;
        xo[c] = to_tf32(v[i] * scale * gamma[c]);
    }
}

// ---------------------------------------------------------------------------
// 2) TF32 tensor-core GEMM (unchanged from R2 — validated)
// ---------------------------------------------------------------------------
#define CP_ASYNC16(dst, src) \
    asm volatile("cp.async.cg.shared.global [%0], [%1], 16;\n" :: "r"(dst), "l"(src))

__global__ __launch_bounds__(256) void gemm_tf32(
    const float* __restrict__ A, const float* __restrict__ B,
    float* __restrict__ C, int M, int N, int K)
{
    __shared__ float As[2][128][20];
    __shared__ float Bs[2][16][136];

    const int t    = threadIdx.x;
    const int lane = t & 31;
    const int warp = t >> 5;
    const int wm   = (warp >> 2) * 64;
    const int wn   = (warp & 3) * 32;
    const int grp  = lane >> 2;
    const int qd   = lane & 3;

    const int brow = blockIdx.y * 128;
    const int bcol = blockIdx.x * 128;

    const uint32_t As_b = (uint32_t)__cvta_generic_to_shared(&As[0][0][0]);
    const uint32_t Bs_b = (uint32_t)__cvta_generic_to_shared(&Bs[0][0][0]);

    float acc[4][4][4];
#pragma unroll
    for (int i = 0; i < 4; i++)
#pragma unroll
        for (int j = 0; j < 4; j++)
#pragma unroll
            for (int r = 0; r < 4; r++) acc[i][j][r] = 0.f;

    auto copy_stage = [&](int k0, int buf) {
#pragma unroll
        for (int i = 0; i < 2; i++) {
            const int c  = t + 256 * i;
            const int r  = c >> 2;
            const int ko = (c & 3) << 2;
            const float* src = A + (size_t)(brow + r) * K + k0 + ko;
            CP_ASYNC16(As_b + (((buf << 7) + r) * 20 + ko) * 4, src);
        }
#pragma unroll
        for (int i = 0; i < 2; i++) {
            const int c  = t + 256 * i;
            const int r  = c >> 5;
            const int no = (c & 31) << 2;
            const float* src = B + (size_t)(k0 + r) * N + bcol + no;
            CP_ASYNC16(Bs_b + (((buf << 4) + r) * 136 + no) * 4, src);
        }
    };

    const int nIter = K >> 4;
    copy_stage(0, 0);
    asm volatile("cp.async.commit_group;\n");

    for (int it = 0; it < nIter; it++) {
        if (it + 1 < nIter) copy_stage((it + 1) << 4, (it + 1) & 1);
        asm volatile("cp.async.commit_group;\n");
        asm volatile("cp.async.wait_group %0;\n" :: "n"(1));
        __syncthreads();

        const int buf = it & 1;
#pragma unroll
        for (int k8 = 0; k8 < 16; k8 += 8) {
            uint32_t af[4][4], bf[4][2];
#pragma unroll
            for (int mt = 0; mt < 4; mt++) {
                const int rA = wm + mt * 16 + grp;
                af[mt][0] = __float_as_uint(As[buf][rA    ][k8 + qd    ]);
                af[mt][1] = __float_as_uint(As[buf][rA + 8][k8 + qd    ]);
                af[mt][2] = __float_as_uint(As[buf][rA    ][k8 + qd + 4]);
                af[mt][3] = __float_as_uint(As[buf][rA + 8][k8 + qd + 4]);
            }
#pragma unroll
            for (int nt = 0; nt < 4; nt++) {
                const int cB = wn + nt * 8 + grp;
                bf[nt][0] = __float_as_uint(Bs[buf][k8 + qd    ][cB]);
                bf[nt][1] = __float_as_uint(Bs[buf][k8 + qd + 4][cB]);
            }
#pragma unroll
            for (int mt = 0; mt < 4; mt++)
#pragma unroll
                for (int nt = 0; nt < 4; nt++) {
                    asm volatile(
                        "mma.sync.aligned.m16n8k8.row.col.f32.tf32.tf32.f32 "
                        "{%0,%1,%2,%3}, {%4,%5,%6,%7}, {%8,%9}, {%0,%1,%2,%3};\n"
                        : "+f"(acc[mt][nt][0]), "+f"(acc[mt][nt][1]),
                          "+f"(acc[mt][nt][2]), "+f"(acc[mt][nt][3])
                        : "r"(af[mt][0]), "r"(af[mt][1]),
                          "r"(af[mt][2]), "r"(af[mt][3]),
                          "r"(bf[nt][0]), "r"(bf[nt][1]));
                }
        }
        __syncthreads();
    }

#pragma unroll
    for (int mt = 0; mt < 4; mt++) {
        const int row0 = brow + wm + mt * 16 + grp;
#pragma unroll
        for (int nt = 0; nt < 4; nt++) {
            const int col0 = bcol + wn + nt * 8 + qd * 2;
            float2 v0 = {acc[mt][nt][0], acc[mt][nt][1]};
            float2 v1 = {acc[mt][nt][2], acc[mt][nt][3]};
            *(float2*)(C + (size_t)row0 * N + col0)       = v0;
            *(float2*)(C + (size_t)(row0 + 8) * N + col0) = v1;
        }
    }
}

// ---------------------------------------------------------------------------
// 3) RoPE (in-place), fp32
// ---------------------------------------------------------------------------
__global__ __launch_bounds__(256) void rope_kernel(
    float* __restrict__ t, const float* __restrict__ rot, int rowstride)
{
    const int idx = blockIdx.x * 256 + threadIdx.x;
    const int d   = idx & 31;
    const int h   = (idx >> 5) & 31;
    const int row = idx >> 10;
    const int n   = row & (SEQ - 1);
    const float p1 = rot[n * 64 + d];
    const float p2 = rot[n * 64 + d + 32];
    float* base = t + (size_t)row * rowstride + h * 64;
    const float a  = base[d];
    const float bv = base[d + 32];
    base[d]      = a  * __cosf(p1) - bv * __sinf(p1);
    base[d + 32] = bv * __cosf(p2) + a  * __sinf(p2);
}

// ---------------------------------------------------------------------------
// 4) Tensor-core causal flash attention (TF32 mma).
//    CTA = 128 queries x 1 head. 8 warps, each owns 16 query rows.
//    Key tiles of 64. K in smem natural [key][d] (= mma col-major B),
//    V transposed to [d][key], P staged in padded smem (warp-private rows).
// ---------------------------------------------------------------------------
#define PK 68                      // pad: conflict-free frag loads, 16B-aligned rows
#define PP 76                      // pad for Ps A-frag loads
#define KS_F (64 * PK)             // 4352 floats per K buffer
#define SMEM_ATTN ((4 * KS_F + 128 * PP) * 4)   // 108544 bytes

__global__ __launch_bounds__(256) void attn_tc(
    const float* __restrict__ q, const float* __restrict__ kv,
    float* __restrict__ o)
{
    extern __shared__ float sm[];
    float* Ks = sm;                  // [2][64][PK]
    float* Vt = sm + 2 * KS_F;       // [2][64][PK]
    float* Ps = sm + 4 * KS_F;       // [128][PP]
    float* Qs = Ps;                  // alias (used only before main loop)

    const int t    = threadIdx.x;
    const int lane = t & 31;
    const int warp = t >> 5;
    const int grp  = lane >> 2;
    const int qd   = lane & 3;
    const int wm   = warp * 16;

    const int qt = (SEQ / 128 - 1) - blockIdx.x;   // longest CTAs first
    const int h  = blockIdx.y;
    const int b  = blockIdx.z;
    const int q0 = qt * 128;

    const size_t qbase = (size_t)b * SEQ * DIM_INNER + (size_t)h * 64;
    const size_t kbase = (size_t)b * SEQ * (2 * DIM_INNER) + (size_t)h * 64;
    const size_t vbase = kbase + DIM_INNER;

    const uint32_t Ks_b = (uint32_t)__cvta_generic_to_shared(Ks);

    // ---- stage Q tile into smem, extract A-fragments (scaled, tf32) ----
    for (int e = t; e < 2048; e += 256) {
        const int row = e >> 4, d4 = (e & 15) << 2;
        float4 v = *(const float4*)(q + qbase + (size_t)(q0 + row) * DIM_INNER + d4);
        *(float4*)(Qs + row * PK + d4) = v;
    }
    __syncthreads();
    uint32_t af[8][4];
#pragma unroll
    for (int kk = 0; kk < 8; kk++) {
        af[kk][0] = tf32u(Qs[(wm + grp    ) * PK + kk * 8 + qd    ] * 0.125f);
        af[kk][1] = tf32u(Qs[(wm + grp + 8) * PK + kk * 8 + qd    ] * 0.125f);
        af[kk][2] = tf32u(Qs[(wm + grp    ) * PK + kk * 8 + qd + 4] * 0.125f);
        af[kk][3] = tf32u(Qs[(wm + grp + 8) * PK + kk * 8 + qd + 4] * 0.125f);
    }
    __syncthreads();   // Qs dead -> Ps live

    float Oacc[8][4];
#pragma unroll
    for (int i = 0; i < 8; i++)
#pragma unroll
        for (int c = 0; c < 4; c++) Oacc[i][c] = 0.f;
    float m0 = -INFINITY, m1 = -INFINITY, l0 = 0.f, l1 = 0.f;

    const int nT = 2 * (qt + 1);

    // V register prefetch mapping: thread -> (key, 16-dim segment)
    const int vkey = t & 63;
    const int vseg = t >> 6;           // 0..3
    float4 vr[4];

    // prefetch tile 0
    {
#pragma unroll
        for (int i = 0; i < 4; i++) {   // K: 1024 float4 / 256 thr
            const int e = t + 256 * i;
            const int key = e >> 4, d4 = (e & 15) << 2;
            CP_ASYNC16(Ks_b + (key * PK + d4) * 4,
                       kv + kbase + (size_t)key * (2 * DIM_INNER) + d4);
        }
        asm volatile("cp.async.commit_group;\n");
#pragma unroll
        for (int i = 0; i < 4; i++)
            vr[i] = *(const float4*)(kv + vbase + (size_t)vkey * (2 * DIM_INNER)
                                     + vseg * 16 + i * 4);
    }

    for (int jt = 0; jt < nT; jt++) {
        const int buf = jt & 1;
        const int j0  = jt * 64;

        // store prefetched V (transposed, tf32-rounded)
        float* vtb = Vt + buf * KS_F;
#pragma unroll
        for (int i = 0; i < 4; i++) {
            const int d0 = vseg * 16 + i * 4;
            vtb[(d0    ) * PK + vkey] = to_tf32(vr[i].x);
            vtb[(d0 + 1) * PK + vkey] = to_tf32(vr[i].y);
            vtb[(d0 + 2) * PK + vkey] = to_tf32(vr[i].z);
            vtb[(d0 + 3) * PK + vkey] = to_tf32(vr[i].w);
        }
        asm volatile("cp.async.wait_group 0;\n");
        __syncthreads();

        // prefetch next tile (after barrier: no one still reads these buffers)
        if (jt + 1 < nT) {
            const int j1 = j0 + 64;
            const uint32_t kdst = Ks_b + (buf ^ 1) * KS_F * 4;
#pragma unroll
            for (int i = 0; i < 4; i++) {
                const int e = t + 256 * i;
                const int key = e >> 4, d4 = (e & 15) << 2;
                CP_ASYNC16(kdst + (key * PK + d4) * 4,
                           kv + kbase + (size_t)(j1 + key) * (2 * DIM_INNER) + d4);
            }
            asm volatile("cp.async.commit_group;\n");
#pragma unroll
            for (int i = 0; i < 4; i++)
                vr[i] = *(const float4*)(kv + vbase
                         + (size_t)(j1 + vkey) * (2 * DIM_INNER) + vseg * 16 + i * 4);
        }

        // ---- S = Q @ K^T ----
        const float* ksb = Ks + buf * KS_F;
        float sa[8][4];
#pragma unroll
        for (int nt = 0; nt < 8; nt++)
#pragma unroll
            for (int c = 0; c < 4; c++) sa[nt][c] = 0.f;
#pragma unroll
        for (int kk = 0; kk < 8; kk++) {
            uint32_t bf[8][2];
#pragma unroll
            for (int nt = 0; nt < 8; nt++) {
                bf[nt][0] = __float_as_uint(ksb[(nt * 8 + grp) * PK + kk * 8 + qd    ]);
                bf[nt][1] = __float_as_uint(ksb[(nt * 8 + grp) * PK + kk * 8 + qd + 4]);
            }
#pragma unroll
            for (int nt = 0; nt < 8; nt++)
                asm volatile(
                    "mma.sync.aligned.m16n8k8.row.col.f32.tf32.tf32.f32 "
                    "{%0,%1,%2,%3}, {%4,%5,%6,%7}, {%8,%9}, {%0,%1,%2,%3};\n"
                    : "+f"(sa[nt][0]), "+f"(sa[nt][1]), "+f"(sa[nt][2]), "+f"(sa[nt][3])
                    : "r"(af[kk][0]), "r"(af[kk][1]), "r"(af[kk][2]), "r"(af[kk][3]),
                      "r"(bf[nt][0]), "r"(bf[nt][1]));
        }

        // causal mask (only the two diagonal tiles need it)
        if (jt >= nT - 2) {
            const int r0 = q0 + wm + grp;
#pragma unroll
            for (int nt = 0; nt < 8; nt++) {
                const int c0 = j0 + nt * 8 + 2 * qd;
                if (c0     > r0    ) sa[nt][0] = -3.0e38f;
                if (c0 + 1 > r0    ) sa[nt][1] = -3.0e38f;
                if (c0     > r0 + 8) sa[nt][2] = -3.0e38f;
                if (c0 + 1 > r0 + 8) sa[nt][3] = -3.0e38f;
            }
        }

        // ---- online softmax ----
        float tm0 = -3.0e38f, tm1 = -3.0e38f;
#pragma unroll
        for (int nt = 0; nt < 8; nt++) {
            tm0 = fmaxf(tm0, fmaxf(sa[nt][0], sa[nt][1]));
            tm1 = fmaxf(tm1, fmaxf(sa[nt][2], sa[nt][3]));
        }
        tm0 = fmaxf(tm0, __shfl_xor_sync(0xffffffffu, tm0, 1));
        tm0 = fmaxf(tm0, __shfl_xor_sync(0xffffffffu, tm0, 2));
        tm1 = fmaxf(tm1, __shfl_xor_sync(0xffffffffu, tm1, 1));
        tm1 = fmaxf(tm1, __shfl_xor_sync(0xffffffffu, tm1, 2));

        const float mn0 = fmaxf(m0, tm0), mn1 = fmaxf(m1, tm1);
        const float a0 = __expf(m0 - mn0), a1 = __expf(m1 - mn1);
        m0 = mn0; m1 = mn1;

        float s0 = 0.f, s1 = 0.f;
        const int pr0 = (wm + grp) * PP, pr1 = (wm + grp + 8) * PP;
#pragma unroll
        for (int nt = 0; nt < 8; nt++) {
            const float p00 = to_tf32(__expf(sa[nt][0] - m0));
            const float p01 = to_tf32(__expf(sa[nt][1] - m0));
            const float p10 = to_tf32(__expf(sa[nt][2] - m1));
            const float p11 = to_tf32(__expf(sa[nt][3] - m1));
            s0 += p00 + p01; s1 += p10 + p11;
            float2 v0 = {p00, p01}, v1 = {p10, p11};
            *(float2*)(Ps + pr0 + nt * 8 + 2 * qd) = v0;
            *(float2*)(Ps + pr1 + nt * 8 + 2 * qd) = v1;
        }
        s0 += __shfl_xor_sync(0xffffffffu, s0, 1);
        s0 += __shfl_xor_sync(0xffffffffu, s0, 2);
        s1 += __shfl_xor_sync(0xffffffffu, s1, 1);
        s1 += __shfl_xor_sync(0xffffffffu, s1, 2);
        l0 = l0 * a0 + s0;
        l1 = l1 * a1 + s1;
#pragma unroll
        for (int i = 0; i < 8; i++) {
            Oacc[i][0] *= a0; Oacc[i][1] *= a0;
            Oacc[i][2] *= a1; Oacc[i][3] *= a1;
        }
        __syncwarp();   // Ps rows are warp-private

        // ---- O += P @ V ----
#pragma unroll
        for (int kk = 0; kk < 8; kk++) {
            uint32_t pa[4];
            pa[0] = __float_as_uint(Ps[pr0 + kk * 8 + qd    ]);
            pa[1] = __float_as_uint(Ps[pr1 + kk * 8 + qd    ]);
            pa[2] = __float_as_uint(Ps[pr0 + kk * 8 + qd + 4]);
            pa[3] = __float_as_uint(Ps[pr1 + kk * 8 + qd + 4]);
            uint32_t vb[8][2];
#pragma unroll
            for (int nt = 0; nt < 8; nt++) {
                vb[nt][0] = __float_as_uint(vtb[(nt * 8 + grp) * PK + kk * 8 + qd    ]);
                vb[nt][1] = __float_as_uint(vtb[(nt * 8 + grp) * PK + kk * 8 + qd + 4]);
            }
#pragma unroll
            for (int nt = 0; nt < 8; nt++)
                asm volatile(
                    "mma.sync.aligned.m16n8k8.row.col.f32.tf32.tf32.f32 "
                    "{%0,%1,%2,%3}, {%4,%5,%6,%7}, {%8,%9}, {%0,%1,%2,%3};\n"
                    : "+f"(Oacc[nt][0]), "+f"(Oacc[nt][1]),
                      "+f"(Oacc[nt][2]), "+f"(Oacc[nt][3])
                    : "r"(pa[0]), "r"(pa[1]), "r"(pa[2]), "r"(pa[3]),
                      "r"(vb[nt][0]), "r"(vb[nt][1]));
        }
        __syncwarp();
    }

    // ---- epilogue: normalize, tf32-round (out-proj input), write ----
    const float inv0 = 1.0f / l0, inv1 = 1.0f / l1;
    const int r0 = q0 + wm + grp, r1 = r0 + 8;
#pragma unroll
    for (int nt = 0; nt < 8; nt++) {
        const int col = nt * 8 + 2 * qd;
        float2 v0 = {to_tf32(Oacc[nt][0] * inv0), to_tf32(Oacc[nt][1] * inv0)};
        float2 v1 = {to_tf32(Oacc[nt][2] * inv1), to_tf32(Oacc[nt][3] * inv1)};
        *(float2*)(o + qbase + (size_t)r0 * DIM_INNER + col) = v0;
        *(float2*)(o + qbase + (size_t)r1 * DIM_INNER + col) = v1;
    }
}

// ---------------------------------------------------------------------------
// Host launcher
// ---------------------------------------------------------------------------
extern "C" void kernel_launch(void* const* d_in, const int* in_sizes, int n_in,
                              void* d_out, int out_size)
{
    const float* x     = (const float*)d_in[0];
    const float* rot   = (const float*)d_in[1];
    const float* gamma = (const float*)d_in[2];
    const float* Wq    = (const float*)d_in[3];
    const float* Wkv   = (const float*)d_in[4];
    const float* Wout  = (const float*)d_in[5];
    float* out = (float*)d_out;

    float *xn, *qb, *kvb, *ob, *wq, *wkv, *wout;
    cudaGetSymbolAddress((void**)&xn,   g_xn);
    cudaGetSymbolAddress((void**)&qb,   g_q);
    cudaGetSymbolAddress((void**)&kvb,  g_kv);
    cudaGetSymbolAddress((void**)&ob,   g_o);
    cudaGetSymbolAddress((void**)&wq,   g_wq);
    cudaGetSymbolAddress((void**)&wkv,  g_wkv);
    cudaGetSymbolAddress((void**)&wout, g_wout);

    static bool attr_set = false;
    if (!attr_set) {
        cudaFuncSetAttribute(attn_tc,
                             cudaFuncAttributeMaxDynamicSharedMemorySize,
                             SMEM_ATTN);
        attr_set = true;
    }

    wcvt_kernel<<<(DIM * DIM_INNER) / 1024, 256>>>(Wq, wq);
    wcvt_kernel<<<(DIM * 2 * DIM_INNER) / 1024, 256>>>(Wkv, wkv);
    wcvt_kernel<<<(DIM_INNER * DIM) / 1024, 256>>>(Wout, wout);
    rmsnorm_kernel<<<ROWS, 256>>>(x, gamma, xn);
    gemm_tf32<<<dim3(DIM_INNER / 128, ROWS / 128), 256>>>(xn, wq,  qb,  ROWS, DIM_INNER,     DIM);
    gemm_tf32<<<dim3(2 * DIM_INNER / 128, ROWS / 128), 256>>>(xn, wkv, kvb, ROWS, 2 * DIM_INNER, DIM);
    rope_kernel<<<(ROWS * 32 * 32) / 256, 256>>>(qb,  rot, DIM_INNER);
    rope_kernel<<<(ROWS * 32 * 32) / 256, 256>>>(kvb, rot, 2 * DIM_INNER);
    attn_tc<<<dim3(SEQ / 128, HEADS, BATCH), 256, SMEM_ATTN>>>(qb, kvb, ob);
    gemm_tf32<<<dim3(DIM / 128, ROWS / 128), 256>>>(ob, wout, out, ROWS, DIM, DIM);
}

// round 5
// speedup vs baseline: 5.4952x; 1.8143x over previous
#include <cuda_runtime.h>
#include <cuda_fp16.h>
#include <math.h>
#include <stdint.h>

// Problem constants
#define DIM       2048
#define HEADS     32
#define DIM_HEAD  64
#define BATCH     2
#define SEQ       2048
#define ROWS      (BATCH * SEQ)          // 4096
#define DIM_INNER (HEADS * DIM_HEAD)     // 2048

// ---------------------------------------------------------------------------
// Scratch (device globals)
// ---------------------------------------------------------------------------
__device__ __half g_xn [ROWS * DIM];            // rmsnorm out (A of proj gemms)
__device__ __half g_q  [ROWS * DIM_INNER];      // q proj (roped, fp16)
__device__ __half g_kv [ROWS * 2 * DIM_INNER];  // k|v proj (k roped, fp16)
__device__ __half g_o  [ROWS * DIM_INNER];      // attn out (A of out gemm)
__device__ __half g_wqT  [DIM_INNER * DIM];     // W^T fp16 [N,K]
__device__ __half g_wkvT [2 * DIM_INNER * DIM];
__device__ __half g_woutT[DIM * DIM_INNER];

__device__ __forceinline__ uint32_t smem_u32(const void* p) {
    return (uint32_t)__cvta_generic_to_shared(p);
}
#define CP_ASYNC16(dst, src) \
    asm volatile("cp.async.cg.shared.global [%0], [%1], 16;\n" :: "r"(dst), "l"(src))

// ---------------------------------------------------------------------------
// 0) Weight transpose + fp16: out[n*K+k] = (half)in[k*N+n]
// ---------------------------------------------------------------------------
__global__ __launch_bounds__(256) void wcvtT_kernel(
    const float* __restrict__ in, __half* __restrict__ out, int K, int N)
{
    __shared__ float tile[32][33];
    const int tx = threadIdx.x & 31, ty = threadIdx.x >> 5;
    const int n0 = blockIdx.x * 32, k0 = blockIdx.y * 32;
#pragma unroll
    for (int i = 0; i < 4; i++)
        tile[ty + 8 * i][tx] = in[(size_t)(k0 + ty + 8 * i) * N + n0 + tx];
    __syncthreads();
#pragma unroll
    for (int i = 0; i < 4; i++)
        out[(size_t)(n0 + ty + 8 * i) * K + k0 + tx] = __float2half(tile[tx][ty + 8 * i]);
}

// ---------------------------------------------------------------------------
// 1) RMSNorm -> fp16
// ---------------------------------------------------------------------------
__global__ __launch_bounds__(256) void rmsnorm_kernel(
    const float* __restrict__ x, const float* __restrict__ gamma,
    __half* __restrict__ xn)
{
    const int row = blockIdx.x;
    const float* xr = x + (size_t)row * DIM;
    float v[8];
    float ss = 0.f;
#pragma unroll
    for (int i = 0; i < 8; i++) {
        v[i] = xr[threadIdx.x + 256 * i];
        ss += v[i] * v[i];
    }
    __shared__ float red[8];
#pragma unroll
    for (int o = 16; o; o >>= 1) ss += __shfl_xor_sync(0xffffffffu, ss, o);
    if ((threadIdx.x & 31) == 0) red[threadIdx.x >> 5] = ss;
    __syncthreads();
    if (threadIdx.x < 32) {
        float s2 = (threadIdx.x < 8) ? red[threadIdx.x] : 0.f;
#pragma unroll
        for (int o = 4; o; o >>= 1) s2 += __shfl_xor_sync(0xffffffffu, s2, o);
        if (threadIdx.x == 0) red[0] = s2;
    }
    __syncthreads();
    const float norm  = sqrtf(red[0]);
    const float scale = 45.25483399593904f / fmaxf(norm, 1e-12f);
    __half* xo = xn + (size_t)row * DIM;
#pragma unroll
    for (int i = 0; i < 8; i++) {
        const int c = threadIdx.x + 256 * i;
        xo[c] = __float2half(v[i] * scale * gamma[c]);
    }
}

// ---------------------------------------------------------------------------
// 2) fp16 tensor-core GEMM: C[M,N] = A[M,K] @ Bt[N,K]^T.
//    CTA 128x128, BK=32 halves, 256 threads (8 warps, 2m x 4n, 64x32 warp tile),
//    mma.m16n8k16, cp.async double-buffered. HOUT: fp16 vs fp32 C.
// ---------------------------------------------------------------------------
#define GPITCH 40    // smem row pitch in halves (80 B: 16B-aligned, conflict-free)

template<bool HOUT>
__global__ __launch_bounds__(256) void gemm_f16(
    const __half* __restrict__ A, const __half* __restrict__ Bt,
    void* __restrict__ Cv, int M, int N, int K)
{
    __shared__ __half As[2][128][GPITCH];
    __shared__ __half Bs[2][128][GPITCH];

    const int t    = threadIdx.x;
    const int lane = t & 31;
    const int warp = t >> 5;
    const int wm   = (warp >> 2) * 64;
    const int wn   = (warp & 3) * 32;
    const int grp  = lane >> 2;
    const int qd   = lane & 3;

    const int brow = blockIdx.y * 128;
    const int bcol = blockIdx.x * 128;

    const uint32_t As_b = smem_u32(&As[0][0][0]);
    const uint32_t Bs_b = smem_u32(&Bs[0][0][0]);

    float acc[4][4][4];
#pragma unroll
    for (int i = 0; i < 4; i++)
#pragma unroll
        for (int j = 0; j < 4; j++)
#pragma unroll
            for (int r = 0; r < 4; r++) acc[i][j][r] = 0.f;

    auto copy_stage = [&](int k0, int buf) {
        const uint32_t ab = As_b + buf * 128 * GPITCH * 2;
        const uint32_t bb = Bs_b + buf * 128 * GPITCH * 2;
#pragma unroll
        for (int i = 0; i < 2; i++) {                 // A: 512 16B-chunks
            const int c = t + 256 * i;
            const int r = c >> 2, s = c & 3;
            CP_ASYNC16(ab + (r * GPITCH + s * 8) * 2,
                       A + (size_t)(brow + r) * K + k0 + s * 8);
        }
#pragma unroll
        for (int i = 0; i < 2; i++) {                 // B: 512 16B-chunks
            const int c = t + 256 * i;
            const int r = c >> 2, s = c & 3;
            CP_ASYNC16(bb + (r * GPITCH + s * 8) * 2,
                       Bt + (size_t)(bcol + r) * K + k0 + s * 8);
        }
    };

    const int S = K >> 5;            // K / 32
    copy_stage(0, 0);
    asm volatile("cp.async.commit_group;\n");

    for (int it = 0; it < S; it++) {
        if (it + 1 < S) copy_stage((it + 1) << 5, (it + 1) & 1);
        asm volatile("cp.async.commit_group;\n");
        asm volatile("cp.async.wait_group %0;\n" :: "n"(1));
        __syncthreads();

        const int buf = it & 1;
#pragma unroll
        for (int ks = 0; ks < 32; ks += 16) {
            uint32_t af[4][4], bf[4][2];
#pragma unroll
            for (int mt = 0; mt < 4; mt++) {
                const int rA = wm + mt * 16 + grp;
                af[mt][0] = *(const uint32_t*)&As[buf][rA    ][ks + qd * 2    ];
                af[mt][1] = *(const uint32_t*)&As[buf][rA + 8][ks + qd * 2    ];
                af[mt][2] = *(const uint32_t*)&As[buf][rA    ][ks + qd * 2 + 8];
                af[mt][3] = *(const uint32_t*)&As[buf][rA + 8][ks + qd * 2 + 8];
            }
#pragma unroll
            for (int nt = 0; nt < 4; nt++) {
                const int rB = wn + nt * 8 + grp;
                bf[nt][0] = *(const uint32_t*)&Bs[buf][rB][ks + qd * 2    ];
                bf[nt][1] = *(const uint32_t*)&Bs[buf][rB][ks + qd * 2 + 8];
            }
#pragma unroll
            for (int mt = 0; mt < 4; mt++)
#pragma unroll
                for (int nt = 0; nt < 4; nt++)
                    asm volatile(
                        "mma.sync.aligned.m16n8k16.row.col.f32.f16.f16.f32 "
                        "{%0,%1,%2,%3}, {%4,%5,%6,%7}, {%8,%9}, {%0,%1,%2,%3};\n"
                        : "+f"(acc[mt][nt][0]), "+f"(acc[mt][nt][1]),
                          "+f"(acc[mt][nt][2]), "+f"(acc[mt][nt][3])
                        : "r"(af[mt][0]), "r"(af[mt][1]),
                          "r"(af[mt][2]), "r"(af[mt][3]),
                          "r"(bf[nt][0]), "r"(bf[nt][1]));
        }
        __syncthreads();
    }

#pragma unroll
    for (int mt = 0; mt < 4; mt++) {
        const int row0 = brow + wm + mt * 16 + grp;
#pragma unroll
        for (int nt = 0; nt < 4; nt++) {
            const int col0 = bcol + wn + nt * 8 + qd * 2;
            if (HOUT) {
                __half* C = (__half*)Cv;
                *(__half2*)(C + (size_t)row0 * N + col0) =
                    __floats2half2_rn(acc[mt][nt][0], acc[mt][nt][1]);
                *(__half2*)(C + (size_t)(row0 + 8) * N + col0) =
                    __floats2half2_rn(acc[mt][nt][2], acc[mt][nt][3]);
            } else {
                float* C = (float*)Cv;
                float2 v0 = {acc[mt][nt][0], acc[mt][nt][1]};
                float2 v1 = {acc[mt][nt][2], acc[mt][nt][3]};
                *(float2*)(C + (size_t)row0 * N + col0)       = v0;
                *(float2*)(C + (size_t)(row0 + 8) * N + col0) = v1;
            }
        }
    }
}

// ---------------------------------------------------------------------------
// 3) RoPE (in-place, fp16 storage, fp32 math)
// ---------------------------------------------------------------------------
__global__ __launch_bounds__(256) void rope_kernel(
    __half* __restrict__ t, const float* __restrict__ rot, int rowstride)
{
    const int idx = blockIdx.x * 256 + threadIdx.x;
    const int d   = idx & 31;
    const int h   = (idx >> 5) & 31;
    const int row = idx >> 10;
    const int n   = row & (SEQ - 1);
    const float p1 = rot[n * 64 + d];
    const float p2 = rot[n * 64 + d + 32];
    __half* base = t + (size_t)row * rowstride + h * 64;
    const float a  = __half2float(base[d]);
    const float bv = __half2float(base[d + 32]);
    base[d]      = __float2half(a  * __cosf(p1) - bv * __sinf(p1));
    base[d + 32] = __float2half(bv * __cosf(p2) + a  * __sinf(p2));
}

// ---------------------------------------------------------------------------
// 4) fp16 tensor-core causal flash attention.
//    CTA = 128 queries x 1 head, 8 warps x 16 rows. 64-key tiles.
//    K natural [key][d] = mma col-major B (direct half2 frags).
//    V natural [key][d] via ldmatrix.x4.trans. P stays in registers (FA2).
// ---------------------------------------------------------------------------
#define APITCH 72                    // halves; 144 B rows (16B-aligned, conflict-free)
#define KTILE_H (64 * APITCH)        // halves per K or V buffer

__global__ __launch_bounds__(256) void attn_f16(
    const __half* __restrict__ q, const __half* __restrict__ kv,
    __half* __restrict__ o)
{
    __shared__ __half smh[4 * KTILE_H];          // Ks0 Vs0 Ks1 Vs1 (36864 B)
    __half* Ks[2] = {smh,               smh + 2 * KTILE_H};
    __half* Vs[2] = {smh + KTILE_H,     smh + 3 * KTILE_H};
    __half* Qs    = smh + 2 * KTILE_H;           // alias over buf1 (pre-loop only)

    const int t    = threadIdx.x;
    const int lane = t & 31;
    const int warp = t >> 5;
    const int grp  = lane >> 2;
    const int qd   = lane & 3;
    const int wm   = warp * 16;

    const int qt = (SEQ / 128 - 1) - blockIdx.x;
    const int h  = blockIdx.y;
    const int b  = blockIdx.z;
    const int q0 = qt * 128;

    const size_t qbase = (size_t)b * SEQ * DIM_INNER + (size_t)h * 64;
    const size_t kbase = (size_t)b * SEQ * (2 * DIM_INNER) + (size_t)h * 64;
    const size_t vbase = kbase + DIM_INNER;

    const uint32_t sm_b = smem_u32(smh);

    auto copy_tile = [&](int j0, int buf) {
        const uint32_t kb = sm_b + (2 * buf)     * KTILE_H * 2;
        const uint32_t vb = sm_b + (2 * buf + 1) * KTILE_H * 2;
#pragma unroll
        for (int i = 0; i < 2; i++) {            // K: 512 chunks
            const int c = t + 256 * i;
            const int r = c >> 3, s = c & 7;
            CP_ASYNC16(kb + (r * APITCH + s * 8) * 2,
                       kv + kbase + (size_t)(j0 + r) * (2 * DIM_INNER) + s * 8);
        }
#pragma unroll
        for (int i = 0; i < 2; i++) {            // V: 512 chunks
            const int c = t + 256 * i;
            const int r = c >> 3, s = c & 7;
            CP_ASYNC16(vb + (r * APITCH + s * 8) * 2,
                       kv + vbase + (size_t)(j0 + r) * (2 * DIM_INNER) + s * 8);
        }
    };

    // ---- stage Q (scaled by 1/8, exact in fp16), extract A-frags ----
    const __half2 hscale = __floats2half2_rn(0.125f, 0.125f);
    for (int e = t; e < 1024; e += 256) {        // 128 rows x 8 halves
        const int row = e >> 3, s = e & 7;
        uint4 u = *(const uint4*)(q + qbase + (size_t)(q0 + row) * DIM_INNER + s * 8);
        __half2* hp = (__half2*)&u;
#pragma unroll
        for (int i = 0; i < 4; i++) hp[i] = __hmul2(hp[i], hscale);
        *(uint4*)(Qs + row * APITCH + s * 8) = u;
    }
    __syncthreads();
    uint32_t af[4][4];
#pragma unroll
    for (int kk = 0; kk < 4; kk++) {
        af[kk][0] = *(const uint32_t*)&Qs[(wm + grp    ) * APITCH + kk * 16 + qd * 2    ];
        af[kk][1] = *(const uint32_t*)&Qs[(wm + grp + 8) * APITCH + kk * 16 + qd * 2    ];
        af[kk][2] = *(const uint32_t*)&Qs[(wm + grp    ) * APITCH + kk * 16 + qd * 2 + 8];
        af[kk][3] = *(const uint32_t*)&Qs[(wm + grp + 8) * APITCH + kk * 16 + qd * 2 + 8];
    }
    __syncthreads();                             // Qs dead; buf1 free for prefetch

    float Oacc[8][4];
#pragma unroll
    for (int i = 0; i < 8; i++)
#pragma unroll
        for (int c = 0; c < 4; c++) Oacc[i][c] = 0.f;
    float m0 = -INFINITY, m1 = -INFINITY, l0 = 0.f, l1 = 0.f;

    const int nT = 2 * (qt + 1);
    copy_tile(0, 0);
    asm volatile("cp.async.commit_group;\n");

    for (int jt = 0; jt < nT; jt++) {
        const int buf = jt & 1;
        const int j0  = jt * 64;

        asm volatile("cp.async.wait_group 0;\n");
        __syncthreads();
        if (jt + 1 < nT) {
            copy_tile(j0 + 64, buf ^ 1);
            asm volatile("cp.async.commit_group;\n");
        }

        // ---- S = Q @ K^T ----
        const __half* ksb = Ks[buf];
        float sa[8][4];
#pragma unroll
        for (int nt = 0; nt < 8; nt++)
#pragma unroll
            for (int c = 0; c < 4; c++) sa[nt][c] = 0.f;
#pragma unroll
        for (int kk = 0; kk < 4; kk++) {
            uint32_t bf[8][2];
#pragma unroll
            for (int nt = 0; nt < 8; nt++) {
                const __half* kr = ksb + (nt * 8 + grp) * APITCH + kk * 16;
                bf[nt][0] = *(const uint32_t*)(kr + qd * 2    );
                bf[nt][1] = *(const uint32_t*)(kr + qd * 2 + 8);
            }
#pragma unroll
            for (int nt = 0; nt < 8; nt++)
                asm volatile(
                    "mma.sync.aligned.m16n8k16.row.col.f32.f16.f16.f32 "
                    "{%0,%1,%2,%3}, {%4,%5,%6,%7}, {%8,%9}, {%0,%1,%2,%3};\n"
                    : "+f"(sa[nt][0]), "+f"(sa[nt][1]), "+f"(sa[nt][2]), "+f"(sa[nt][3])
                    : "r"(af[kk][0]), "r"(af[kk][1]), "r"(af[kk][2]), "r"(af[kk][3]),
                      "r"(bf[nt][0]), "r"(bf[nt][1]));
        }

        // causal mask (diagonal 128-block only)
        if (jt >= nT - 2) {
            const int r0 = q0 + wm + grp;
#pragma unroll
            for (int nt = 0; nt < 8; nt++) {
                const int c0 = j0 + nt * 8 + 2 * qd;
                if (c0     > r0    ) sa[nt][0] = -3.0e38f;
                if (c0 + 1 > r0    ) sa[nt][1] = -3.0e38f;
                if (c0     > r0 + 8) sa[nt][2] = -3.0e38f;
                if (c0 + 1 > r0 + 8) sa[nt][3] = -3.0e38f;
            }
        }

        // ---- online softmax ----
        float tm0 = -3.0e38f, tm1 = -3.0e38f;
#pragma unroll
        for (int nt = 0; nt < 8; nt++) {
            tm0 = fmaxf(tm0, fmaxf(sa[nt][0], sa[nt][1]));
            tm1 = fmaxf(tm1, fmaxf(sa[nt][2], sa[nt][3]));
        }
        tm0 = fmaxf(tm0, __shfl_xor_sync(0xffffffffu, tm0, 1));
        tm0 = fmaxf(tm0, __shfl_xor_sync(0xffffffffu, tm0, 2));
        tm1 = fmaxf(tm1, __shfl_xor_sync(0xffffffffu, tm1, 1));
        tm1 = fmaxf(tm1, __shfl_xor_sync(0xffffffffu, tm1, 2));

        const float mn0 = fmaxf(m0, tm0), mn1 = fmaxf(m1, tm1);
        const float a0 = __expf(m0 - mn0), a1 = __expf(m1 - mn1);
        m0 = mn0; m1 = mn1;

        // P = exp(S-m) -> fp16 (in registers), rounded values feed both l and PV
        uint32_t ph[8][2];                        // [tile][row-pair]: half2
        float s0 = 0.f, s1 = 0.f;
#pragma unroll
        for (int nt = 0; nt < 8; nt++) {
            __half2 p0 = __floats2half2_rn(__expf(sa[nt][0] - m0), __expf(sa[nt][1] - m0));
            __half2 p1 = __floats2half2_rn(__expf(sa[nt][2] - m1), __expf(sa[nt][3] - m1));
            ph[nt][0] = *(uint32_t*)&p0;
            ph[nt][1] = *(uint32_t*)&p1;
            float2 f0 = __half22float2(p0), f1 = __half22float2(p1);
            s0 += f0.x + f0.y; s1 += f1.x + f1.y;
        }
        s0 += __shfl_xor_sync(0xffffffffu, s0, 1);
        s0 += __shfl_xor_sync(0xffffffffu, s0, 2);
        s1 += __shfl_xor_sync(0xffffffffu, s1, 1);
        s1 += __shfl_xor_sync(0xffffffffu, s1, 2);
        l0 = l0 * a0 + s0;
        l1 = l1 * a1 + s1;
#pragma unroll
        for (int i = 0; i < 8; i++) {
            Oacc[i][0] *= a0; Oacc[i][1] *= a0;
            Oacc[i][2] *= a1; Oacc[i][3] *= a1;
        }

        // ---- O += P @ V ----  (V B-frags via ldmatrix.x4.trans)
        const uint32_t vsb = sm_b + (2 * buf + 1) * KTILE_H * 2;
#pragma unroll
        for (int kk = 0; kk < 4; kk++) {
            const uint32_t pa0 = ph[2 * kk][0],     pa1 = ph[2 * kk][1];
            const uint32_t pa2 = ph[2 * kk + 1][0], pa3 = ph[2 * kk + 1][1];
#pragma unroll
            for (int nt2 = 0; nt2 < 4; nt2++) {
                uint32_t vb0, vb1, vb2, vb3;
                const uint32_t addr = vsb
                    + ((kk * 16 + (lane & 15)) * APITCH + nt2 * 16 + (lane >> 4) * 8) * 2;
                asm volatile(
                    "ldmatrix.sync.aligned.m8n8.x4.trans.shared.b16 {%0,%1,%2,%3}, [%4];"
                    : "=r"(vb0), "=r"(vb1), "=r"(vb2), "=r"(vb3) : "r"(addr));
                asm volatile(
                    "mma.sync.aligned.m16n8k16.row.col.f32.f16.f16.f32 "
                    "{%0,%1,%2,%3}, {%4,%5,%6,%7}, {%8,%9}, {%0,%1,%2,%3};\n"
                    : "+f"(Oacc[nt2 * 2][0]), "+f"(Oacc[nt2 * 2][1]),
                      "+f"(Oacc[nt2 * 2][2]), "+f"(Oacc[nt2 * 2][3])
                    : "r"(pa0), "r"(pa1), "r"(pa2), "r"(pa3), "r"(vb0), "r"(vb1));
                asm volatile(
                    "mma.sync.aligned.m16n8k16.row.col.f32.f16.f16.f32 "
                    "{%0,%1,%2,%3}, {%4,%5,%6,%7}, {%8,%9}, {%0,%1,%2,%3};\n"
                    : "+f"(Oacc[nt2 * 2 + 1][0]), "+f"(Oacc[nt2 * 2 + 1][1]),
                      "+f"(Oacc[nt2 * 2 + 1][2]), "+f"(Oacc[nt2 * 2 + 1][3])
                    : "r"(pa0), "r"(pa1), "r"(pa2), "r"(pa3), "r"(vb2), "r"(vb3));
            }
        }
        __syncthreads();   // all warps done with this buffer before next prefetch lands
    }

    // ---- epilogue ----
    const float inv0 = 1.0f / l0, inv1 = 1.0f / l1;
    const int r0 = q0 + wm + grp, r1 = r0 + 8;
#pragma unroll
    for (int nt = 0; nt < 8; nt++) {
        const int col = nt * 8 + 2 * qd;
        *(__half2*)(o + qbase + (size_t)r0 * DIM_INNER + col) =
            __floats2half2_rn(Oacc[nt][0] * inv0, Oacc[nt][1] * inv0);
        *(__half2*)(o + qbase + (size_t)r1 * DIM_INNER + col) =
            __floats2half2_rn(Oacc[nt][2] * inv1, Oacc[nt][3] * inv1);
    }
}

// ---------------------------------------------------------------------------
// Host launcher
// ---------------------------------------------------------------------------
extern "C" void kernel_launch(void* const* d_in, const int* in_sizes, int n_in,
                              void* d_out, int out_size)
{
    const float* x     = (const float*)d_in[0];
    const float* rot   = (const float*)d_in[1];
    const float* gamma = (const float*)d_in[2];
    const float* Wq    = (const float*)d_in[3];
    const float* Wkv   = (const float*)d_in[4];
    const float* Wout  = (const float*)d_in[5];
    float* out = (float*)d_out;

    __half *xn, *qb, *kvb, *ob, *wqT, *wkvT, *woutT;
    cudaGetSymbolAddress((void**)&xn,    g_xn);
    cudaGetSymbolAddress((void**)&qb,    g_q);
    cudaGetSymbolAddress((void**)&kvb,   g_kv);
    cudaGetSymbolAddress((void**)&ob,    g_o);
    cudaGetSymbolAddress((void**)&wqT,   g_wqT);
    cudaGetSymbolAddress((void**)&wkvT,  g_wkvT);
    cudaGetSymbolAddress((void**)&woutT, g_woutT);

    // 0) transpose + fp16 weights
    wcvtT_kernel<<<dim3(DIM_INNER / 32, DIM / 32), 256>>>(Wq,   wqT,   DIM, DIM_INNER);
    wcvtT_kernel<<<dim3(2 * DIM_INNER / 32, DIM / 32), 256>>>(Wkv, wkvT, DIM, 2 * DIM_INNER);
    wcvtT_kernel<<<dim3(DIM / 32, DIM_INNER / 32), 256>>>(Wout, woutT, DIM_INNER, DIM);
    // 1) rmsnorm -> fp16
    rmsnorm_kernel<<<ROWS, 256>>>(x, gamma, xn);
    // 2) projections (fp16 out)
    gemm_f16<true><<<dim3(DIM_INNER / 128, ROWS / 128), 256>>>(
        xn, wqT, qb, ROWS, DIM_INNER, DIM);
    gemm_f16<true><<<dim3(2 * DIM_INNER / 128, ROWS / 128), 256>>>(
        xn, wkvT, kvb, ROWS, 2 * DIM_INNER, DIM);
    // 3) RoPE (fp16 in-place)
    rope_kernel<<<(ROWS * 32 * 32) / 256, 256>>>(qb,  rot, DIM_INNER);
    rope_kernel<<<(ROWS * 32 * 32) / 256, 256>>>(kvb, rot, 2 * DIM_INNER);
    // 4) attention (fp16 mma, fp32 softmax/accum)
    attn_f16<<<dim3(SEQ / 128, HEADS, BATCH), 256>>>(qb, kvb, ob);
    // 5) out projection (fp32 out)
    gemm_f16<false><<<dim3(DIM / 128, ROWS / 128), 256>>>(
        ob, woutT, out, ROWS, DIM, DIM);
}